// round 1
// baseline (speedup 1.0000x reference)
#include <cuda_runtime.h>
#include <math.h>

#define T_LEN 8192
#define EMB   512
#define HID   2048
#define NCH   256
#define ZDIM  2560        // EMB + HID
#define NBLK  128         // persistent CTAs (<=148 SMs, single wave)
#define UPB   16          // hidden units per block (128*16 = 2048)

// ---- static scratch (no runtime allocation allowed) ----
__device__ float    g_Gx[(size_t)T_LEN * 4 * HID];   // 256 MB: precomputed x-part + bias
__device__ float    g_H [(size_t)T_LEN * HID];       // 64 MB: all h_t for final Y GEMM
__device__ float    g_hbuf[2][HID];                  // double-buffered h broadcast
__device__ unsigned g_cnt;                           // grid barrier counter (monotonic)

// ------------------------------------------------------------------
// init: reset barrier counter + zero initial h (must re-run per replay)
// ------------------------------------------------------------------
__global__ void init_kernel() {
    int tid = threadIdx.x;
    if (tid == 0) g_cnt = 0u;
    for (int i = tid; i < HID; i += blockDim.x) {
        g_hbuf[0][i] = 0.f;
        g_hbuf[1][i] = 0.f;
    }
}

// ------------------------------------------------------------------
// Gx[t, gate*H + j] = b_gate[j] + sum_{k<512} emb[seq[t]][k] * W_gate[j][k]
// gate order: 0=f, 1=i, 2=c~, 3=o.  Tile 64(t) x 64(row), K chunks of 32.
// ------------------------------------------------------------------
__global__ void gx_kernel(const int* __restrict__ seq, const float* __restrict__ emb,
                          const float* __restrict__ Wf, const float* __restrict__ Wi,
                          const float* __restrict__ Wc, const float* __restrict__ Wo,
                          const float* __restrict__ bf, const float* __restrict__ bi,
                          const float* __restrict__ bc, const float* __restrict__ bo)
{
    __shared__ float xs[64][33];
    __shared__ float ws[64][33];
    __shared__ int   ss[64];
    __shared__ float bias_s[64];

    const int tid = threadIdx.x;
    const int t0 = blockIdx.x * 64;
    const int r0 = blockIdx.y * 64;
    const int gate = r0 >> 11;          // 64 | 2048 so tile never straddles gates
    const int j0 = r0 & (HID - 1);

    const float* W  = (gate == 0) ? Wf : (gate == 1) ? Wi : (gate == 2) ? Wc : Wo;
    const float* bb = (gate == 0) ? bf : (gate == 1) ? bi : (gate == 2) ? bc : bo;

    if (tid < 64) { ss[tid] = seq[t0 + tid]; bias_s[tid] = bb[j0 + tid]; }

    const int tx = tid & 15, ty = tid >> 4;
    float acc[4][4];
    #pragma unroll
    for (int e = 0; e < 4; ++e)
        #pragma unroll
        for (int f = 0; f < 4; ++f) acc[e][f] = 0.f;

    for (int kc = 0; kc < EMB; kc += 32) {
        __syncthreads();   // protects ss/bias_s first pass + smem reuse
        #pragma unroll
        for (int i = 0; i < 8; ++i) {
            int l = tid + 256 * i;
            int row = l >> 5, col = l & 31;
            xs[row][col] = emb[(size_t)ss[row] * EMB + kc + col];
            ws[row][col] = W[(size_t)(j0 + row) * ZDIM + kc + col];
        }
        __syncthreads();
        #pragma unroll
        for (int k = 0; k < 32; ++k) {
            float a[4], b[4];
            #pragma unroll
            for (int e = 0; e < 4; ++e) a[e] = xs[ty * 4 + e][k];
            #pragma unroll
            for (int f = 0; f < 4; ++f) b[f] = ws[tx * 4 + f][k];
            #pragma unroll
            for (int e = 0; e < 4; ++e)
                #pragma unroll
                for (int f = 0; f < 4; ++f) acc[e][f] = fmaf(a[e], b[f], acc[e][f]);
        }
    }
    __syncthreads();
    #pragma unroll
    for (int e = 0; e < 4; ++e)
        #pragma unroll
        for (int f = 0; f < 4; ++f) {
            int t = t0 + ty * 4 + e;
            int r = r0 + tx * 4 + f;
            g_Gx[(size_t)t * (4 * HID) + r] = acc[e][f] + bias_s[tx * 4 + f];
        }
}

// ------------------------------------------------------------------
// Persistent sequential LSTM loop. 128 CTAs, each owns 16 hidden units
// (64 gate rows). One grid barrier per step; h double-buffered.
// ------------------------------------------------------------------
__global__ void __launch_bounds__(256, 1) lstm_loop(
    const float* __restrict__ Wf, const float* __restrict__ Wi,
    const float* __restrict__ Wc, const float* __restrict__ Wo,
    float* __restrict__ out)
{
    __shared__ float h_s[HID];
    __shared__ float g_s[64];
    __shared__ float gx_s[64];
    __shared__ float c_s[UPB];

    const int tid  = threadIdx.x;
    const int lane = tid & 31;
    const int w    = tid >> 5;          // warp 0..7
    const int blk  = blockIdx.x;
    const int gate = w >> 1;            // 0..3 = f,i,c~,o
    const int u0   = (w & 1) * 8;       // 8 rows per warp

    const float* Wg = (gate == 0) ? Wf : (gate == 1) ? Wi : (gate == 2) ? Wc : Wo;
    const float4* row4[8];
    #pragma unroll
    for (int r = 0; r < 8; ++r)
        row4[r] = (const float4*)(Wg + (size_t)(blk * UPB + u0 + r) * ZDIM + EMB);

    for (int i = tid; i < HID; i += 256) h_s[i] = 0.f;   // h_{-1} = 0
    if (tid < UPB) c_s[tid] = 0.f;
    __syncthreads();

    const float4* hs4 = (const float4*)h_s;

    for (int t = 0; t < T_LEN; ++t) {
        // prefetch Gx for this step (consumed after the next barrier-free sync)
        if (tid < 64)
            gx_s[tid] = __ldg(&g_Gx[(size_t)t * (4 * HID) + (tid >> 4) * HID
                                    + blk * UPB + (tid & 15)]);

        // ---- 64 dot products of length 2048 (h-part only) ----
        float4 acc[8];
        #pragma unroll
        for (int r = 0; r < 8; ++r) acc[r] = make_float4(0.f, 0.f, 0.f, 0.f);

        #pragma unroll 2
        for (int kk = 0; kk < 16; ++kk) {
            float4 h4 = hs4[kk * 32 + lane];
            #pragma unroll
            for (int r = 0; r < 8; ++r) {
                float4 w4 = row4[r][kk * 32 + lane];
                acc[r].x = fmaf(w4.x, h4.x, acc[r].x);
                acc[r].y = fmaf(w4.y, h4.y, acc[r].y);
                acc[r].z = fmaf(w4.z, h4.z, acc[r].z);
                acc[r].w = fmaf(w4.w, h4.w, acc[r].w);
            }
        }
        #pragma unroll
        for (int r = 0; r < 8; ++r) {
            float s = (acc[r].x + acc[r].y) + (acc[r].z + acc[r].w);
            s += __shfl_xor_sync(0xFFFFFFFFu, s, 16);
            s += __shfl_xor_sync(0xFFFFFFFFu, s, 8);
            s += __shfl_xor_sync(0xFFFFFFFFu, s, 4);
            s += __shfl_xor_sync(0xFFFFFFFFu, s, 2);
            s += __shfl_xor_sync(0xFFFFFFFFu, s, 1);
            if (lane == 0) g_s[gate * 16 + u0 + r] = s;
        }
        __syncthreads();

        // ---- pointwise gates (16 threads, one per owned unit) ----
        if (tid < UPB) {
            int j = blk * UPB + tid;
            float gf = g_s[tid]      + gx_s[tid];
            float gi = g_s[16 + tid] + gx_s[16 + tid];
            float gc = g_s[32 + tid] + gx_s[32 + tid];
            float go = g_s[48 + tid] + gx_s[48 + tid];
            float f_  = 1.f / (1.f + expf(-gf));
            float i_  = 1.f / (1.f + expf(-gi));
            float ct  = tanhf(gc);
            float o_  = 1.f / (1.f + expf(-go));
            float c   = f_ * c_s[tid] + i_ * ct;
            c_s[tid]  = c;
            float h   = o_ * tanhf(c);
            g_hbuf[t & 1][j] = h;
            g_H[(size_t)t * HID + j] = h;
            if (t == T_LEN - 1) {
                out[(size_t)T_LEN * NCH + j]       = h;   // final h
                out[(size_t)T_LEN * NCH + HID + j] = c;   // final c
            }
        }
        __syncthreads();

        // ---- grid barrier: all h(t) stores visible before anyone reads ----
        if (tid == 0) {
            __threadfence();
            atomicAdd(&g_cnt, 1u);
            unsigned target = (unsigned)(t + 1) * NBLK;
            while (*((volatile unsigned*)&g_cnt) < target) { }
            __threadfence();
        }
        __syncthreads();

        // ---- reload full h(t) into smem (bypass L1: other SMs wrote it) ----
        {
            const float4* src = (const float4*)g_hbuf[t & 1];
            float4* dst = (float4*)h_s;
            for (int i = tid; i < HID / 4; i += 256) dst[i] = __ldcg(&src[i]);
        }
        __syncthreads();
    }
}

// ------------------------------------------------------------------
// Y[t][n] = b_y[n] + sum_k H[t][k] * W_y[n][k]
// ------------------------------------------------------------------
__global__ void y_kernel(const float* __restrict__ Wy, const float* __restrict__ by,
                         float* __restrict__ out)
{
    __shared__ float as[64][33];
    __shared__ float ws[64][33];
    __shared__ float bias_s[64];

    const int tid = threadIdx.x;
    const int t0 = blockIdx.x * 64;
    const int n0 = blockIdx.y * 64;
    if (tid < 64) bias_s[tid] = by[n0 + tid];

    const int tx = tid & 15, ty = tid >> 4;
    float acc[4][4];
    #pragma unroll
    for (int e = 0; e < 4; ++e)
        #pragma unroll
        for (int f = 0; f < 4; ++f) acc[e][f] = 0.f;

    for (int kc = 0; kc < HID; kc += 32) {
        __syncthreads();
        #pragma unroll
        for (int i = 0; i < 8; ++i) {
            int l = tid + 256 * i;
            int row = l >> 5, col = l & 31;
            as[row][col] = g_H[(size_t)(t0 + row) * HID + kc + col];
            ws[row][col] = Wy[(size_t)(n0 + row) * HID + kc + col];
        }
        __syncthreads();
        #pragma unroll
        for (int k = 0; k < 32; ++k) {
            float a[4], b[4];
            #pragma unroll
            for (int e = 0; e < 4; ++e) a[e] = as[ty * 4 + e][k];
            #pragma unroll
            for (int f = 0; f < 4; ++f) b[f] = ws[tx * 4 + f][k];
            #pragma unroll
            for (int e = 0; e < 4; ++e)
                #pragma unroll
                for (int f = 0; f < 4; ++f) acc[e][f] = fmaf(a[e], b[f], acc[e][f]);
        }
    }
    __syncthreads();
    #pragma unroll
    for (int e = 0; e < 4; ++e)
        #pragma unroll
        for (int f = 0; f < 4; ++f)
            out[(size_t)(t0 + ty * 4 + e) * NCH + n0 + tx * 4 + f]
                = acc[e][f] + bias_s[tx * 4 + f];
}

// ------------------------------------------------------------------
extern "C" void kernel_launch(void* const* d_in, const int* in_sizes, int n_in,
                              void* d_out, int out_size)
{
    const int*   seq = (const int*)  d_in[0];
    const float* emb = (const float*)d_in[1];
    const float* Wf  = (const float*)d_in[2];
    const float* bf  = (const float*)d_in[3];
    const float* Wi  = (const float*)d_in[4];
    const float* bi  = (const float*)d_in[5];
    const float* Wo  = (const float*)d_in[6];
    const float* bo  = (const float*)d_in[7];
    const float* Wc  = (const float*)d_in[8];
    const float* bc  = (const float*)d_in[9];
    const float* Wy  = (const float*)d_in[10];
    const float* by  = (const float*)d_in[11];
    float* out = (float*)d_out;

    init_kernel<<<1, 256>>>();

    dim3 ggx(T_LEN / 64, (4 * HID) / 64);          // 128 x 128
    gx_kernel<<<ggx, 256>>>(seq, emb, Wf, Wi, Wc, Wo, bf, bi, bc, bo);

    lstm_loop<<<NBLK, 256>>>(Wf, Wi, Wc, Wo, out);

    dim3 gy(T_LEN / 64, NCH / 64);                 // 128 x 4
    y_kernel<<<gy, 256>>>(Wy, by, out);
}

// round 2
// speedup vs baseline: 1.3254x; 1.3254x over previous
#include <cuda_runtime.h>
#include <cuda_fp16.h>
#include <math.h>

#define T_LEN 8192
#define EMB   512
#define HID   2048
#define NCH   256
#define ZDIM  2560        // EMB + HID
#define NBLK  128         // persistent CTAs (<=148 SMs, single wave)
#define UPB   16          // hidden units per block (128*16 = 2048)
#define SROWS 48          // gate rows per CTA kept resident in SMEM (of 64)

// ---- static scratch (no runtime allocation allowed) ----
__device__ float    g_Gx[(size_t)T_LEN * 4 * HID];   // 256 MB: precomputed x-part + bias
__device__ float    g_H [(size_t)T_LEN * HID];       // 64 MB: all h_t for final Y GEMM
__device__ __half   g_Wh[(size_t)4 * HID * HID];     // 32 MB: fp16 recurrent weights
__device__ float    g_hbuf[2][HID];                  // double-buffered h broadcast
__device__ unsigned g_cnt;                           // grid barrier counter (monotonic)

// ------------------------------------------------------------------
// init: reset barrier counter + zero initial h (must re-run per replay)
// ------------------------------------------------------------------
__global__ void init_kernel() {
    int tid = threadIdx.x;
    if (tid == 0) g_cnt = 0u;
    for (int i = tid; i < HID; i += blockDim.x) {
        g_hbuf[0][i] = 0.f;
        g_hbuf[1][i] = 0.f;
    }
}

// ------------------------------------------------------------------
// prep: convert recurrent halves of W_f/i/c/o (cols EMB..ZDIM) to fp16.
// g_Wh row R = gate*HID + j (gate order f,i,c,o), 2048 halves per row.
// ------------------------------------------------------------------
__global__ void prep_kernel(const float* __restrict__ Wf, const float* __restrict__ Wi,
                            const float* __restrict__ Wc, const float* __restrict__ Wo)
{
    const int R = blockIdx.x;                 // 0 .. 4*HID-1
    const int gate = R >> 11;                 // HID = 2048
    const int j = R & (HID - 1);
    const float* W = (gate == 0) ? Wf : (gate == 1) ? Wi : (gate == 2) ? Wc : Wo;
    const float4* src = (const float4*)(W + (size_t)j * ZDIM + EMB);
    __half* dst = g_Wh + (size_t)R * HID;

    for (int c4 = threadIdx.x; c4 < HID / 4; c4 += blockDim.x) {
        float4 v = src[c4];
        __half2 lo = __floats2half2_rn(v.x, v.y);
        __half2 hi = __floats2half2_rn(v.z, v.w);
        *(uint2*)(dst + c4 * 4) = make_uint2(*(unsigned*)&lo, *(unsigned*)&hi);
    }
}

// ------------------------------------------------------------------
// Gx[t, gate*H + j] = b_gate[j] + sum_{k<512} emb[seq[t]][k] * W_gate[j][k]
// ------------------------------------------------------------------
__global__ void gx_kernel(const int* __restrict__ seq, const float* __restrict__ emb,
                          const float* __restrict__ Wf, const float* __restrict__ Wi,
                          const float* __restrict__ Wc, const float* __restrict__ Wo,
                          const float* __restrict__ bf, const float* __restrict__ bi,
                          const float* __restrict__ bc, const float* __restrict__ bo)
{
    __shared__ float xs[64][33];
    __shared__ float ws[64][33];
    __shared__ int   ss[64];
    __shared__ float bias_s[64];

    const int tid = threadIdx.x;
    const int t0 = blockIdx.x * 64;
    const int r0 = blockIdx.y * 64;
    const int gate = r0 >> 11;
    const int j0 = r0 & (HID - 1);

    const float* W  = (gate == 0) ? Wf : (gate == 1) ? Wi : (gate == 2) ? Wc : Wo;
    const float* bb = (gate == 0) ? bf : (gate == 1) ? bi : (gate == 2) ? bc : bo;

    if (tid < 64) { ss[tid] = seq[t0 + tid]; bias_s[tid] = bb[j0 + tid]; }

    const int tx = tid & 15, ty = tid >> 4;
    float acc[4][4];
    #pragma unroll
    for (int e = 0; e < 4; ++e)
        #pragma unroll
        for (int f = 0; f < 4; ++f) acc[e][f] = 0.f;

    for (int kc = 0; kc < EMB; kc += 32) {
        __syncthreads();
        #pragma unroll
        for (int i = 0; i < 8; ++i) {
            int l = tid + 256 * i;
            int row = l >> 5, col = l & 31;
            xs[row][col] = emb[(size_t)ss[row] * EMB + kc + col];
            ws[row][col] = W[(size_t)(j0 + row) * ZDIM + kc + col];
        }
        __syncthreads();
        #pragma unroll
        for (int k = 0; k < 32; ++k) {
            float a[4], b[4];
            #pragma unroll
            for (int e = 0; e < 4; ++e) a[e] = xs[ty * 4 + e][k];
            #pragma unroll
            for (int f = 0; f < 4; ++f) b[f] = ws[tx * 4 + f][k];
            #pragma unroll
            for (int e = 0; e < 4; ++e)
                #pragma unroll
                for (int f = 0; f < 4; ++f) acc[e][f] = fmaf(a[e], b[f], acc[e][f]);
        }
    }
    __syncthreads();
    #pragma unroll
    for (int e = 0; e < 4; ++e)
        #pragma unroll
        for (int f = 0; f < 4; ++f) {
            int t = t0 + ty * 4 + e;
            int r = r0 + tx * 4 + f;
            g_Gx[(size_t)t * (4 * HID) + r] = acc[e][f] + bias_s[tx * 4 + f];
        }
}

// ------------------------------------------------------------------
// Persistent sequential LSTM loop. 128 CTAs x 256 threads.
// CTA owns 16 hidden units = 64 gate rows (R = gate*16 + unit, R in 0..63).
// Rows 0..47 live in SMEM (fp16, loaded once); rows 48..63 stream from L2.
// Warp w handles rows w*8..w*8+7  ->  warps 0..5 SMEM, warps 6..7 global.
// ------------------------------------------------------------------
extern __shared__ unsigned char dynsmem[];

__global__ void __launch_bounds__(256, 1) lstm_loop(float* __restrict__ out)
{
    __half* ws  = (__half*)dynsmem;                               // [SROWS][HID]
    float*  h_s = (float*)(dynsmem + (size_t)SROWS * HID * 2);    // [HID]
    __shared__ float g_s[64];
    __shared__ float gx_s[64];
    __shared__ float c_s[UPB];

    const int tid  = threadIdx.x;
    const int lane = tid & 31;
    const int w    = tid >> 5;
    const int blk  = blockIdx.x;
    const int base = w * 8;                  // first CTA-row for this warp

    // ---- one-time: copy 48 rows of fp16 weights into SMEM ----
    for (int idx = tid; idx < SROWS * (HID / 8); idx += 256) {
        int R  = idx / (HID / 8);
        int c8 = idx % (HID / 8);
        int gate = R >> 4, unit = R & 15;
        const uint4* src = (const uint4*)(g_Wh + ((size_t)(gate * HID + blk * UPB + unit)) * HID);
        ((uint4*)(ws + (size_t)R * HID))[c8] = src[c8];
    }

    // global row pointers for streamed rows (warps 6,7: base >= SROWS)
    const __half* gp[8];
    #pragma unroll
    for (int r = 0; r < 8; ++r) {
        int R = base + r;
        int gate = R >> 4, unit = R & 15;
        gp[r] = g_Wh + ((size_t)(gate * HID + blk * UPB + unit)) * HID;
    }

    for (int i = tid; i < HID; i += 256) h_s[i] = 0.f;   // h_{-1} = 0
    if (tid < UPB) c_s[tid] = 0.f;
    __syncthreads();

    for (int t = 0; t < T_LEN; ++t) {
        // prefetch Gx for this step
        if (tid < 64)
            gx_s[tid] = __ldg(&g_Gx[(size_t)t * (4 * HID) + (tid >> 4) * HID
                                    + blk * UPB + (tid & 15)]);

        // ---- 8 dot products of length 2048 per warp ----
        float4 acc[8];
        #pragma unroll
        for (int r = 0; r < 8; ++r) acc[r] = make_float4(0.f, 0.f, 0.f, 0.f);

        if (w < 6) {
            // SMEM-resident rows
            const __half* wrow = ws + (size_t)base * HID;
            #pragma unroll 4
            for (int kk = 0; kk < 16; ++kk) {
                const int off = kk * 128 + lane * 4;
                float4 h4 = *(const float4*)(h_s + off);
                #pragma unroll
                for (int r = 0; r < 8; ++r) {
                    uint2 wv = *(const uint2*)(wrow + (size_t)r * HID + off);
                    float2 f01 = __half22float2(*(const __half2*)&wv.x);
                    float2 f23 = __half22float2(*(const __half2*)&wv.y);
                    acc[r].x = fmaf(f01.x, h4.x, acc[r].x);
                    acc[r].y = fmaf(f01.y, h4.y, acc[r].y);
                    acc[r].z = fmaf(f23.x, h4.z, acc[r].z);
                    acc[r].w = fmaf(f23.y, h4.w, acc[r].w);
                }
            }
        } else {
            // L2-streamed rows
            #pragma unroll 2
            for (int kk = 0; kk < 16; ++kk) {
                const int off = kk * 128 + lane * 4;
                float4 h4 = *(const float4*)(h_s + off);
                #pragma unroll
                for (int r = 0; r < 8; ++r) {
                    uint2 wv = __ldg((const uint2*)(gp[r] + off));
                    float2 f01 = __half22float2(*(const __half2*)&wv.x);
                    float2 f23 = __half22float2(*(const __half2*)&wv.y);
                    acc[r].x = fmaf(f01.x, h4.x, acc[r].x);
                    acc[r].y = fmaf(f01.y, h4.y, acc[r].y);
                    acc[r].z = fmaf(f23.x, h4.z, acc[r].z);
                    acc[r].w = fmaf(f23.y, h4.w, acc[r].w);
                }
            }
        }

        #pragma unroll
        for (int r = 0; r < 8; ++r) {
            float s = (acc[r].x + acc[r].y) + (acc[r].z + acc[r].w);
            s += __shfl_xor_sync(0xFFFFFFFFu, s, 16);
            s += __shfl_xor_sync(0xFFFFFFFFu, s, 8);
            s += __shfl_xor_sync(0xFFFFFFFFu, s, 4);
            s += __shfl_xor_sync(0xFFFFFFFFu, s, 2);
            s += __shfl_xor_sync(0xFFFFFFFFu, s, 1);
            if (lane == 0) g_s[base + r] = s;
        }
        __syncthreads();

        // ---- pointwise gates (16 threads, one per owned unit) ----
        if (tid < UPB) {
            int j = blk * UPB + tid;
            float gf = g_s[tid]      + gx_s[tid];
            float gi = g_s[16 + tid] + gx_s[16 + tid];
            float gc = g_s[32 + tid] + gx_s[32 + tid];
            float go = g_s[48 + tid] + gx_s[48 + tid];
            float f_  = 1.f / (1.f + expf(-gf));
            float i_  = 1.f / (1.f + expf(-gi));
            float ct  = tanhf(gc);
            float o_  = 1.f / (1.f + expf(-go));
            float c   = f_ * c_s[tid] + i_ * ct;
            c_s[tid]  = c;
            float h   = o_ * tanhf(c);
            g_hbuf[t & 1][j] = h;
            g_H[(size_t)t * HID + j] = h;
            if (t == T_LEN - 1) {
                out[(size_t)T_LEN * NCH + j]       = h;   // final h
                out[(size_t)T_LEN * NCH + HID + j] = c;   // final c
            }
        }
        __syncthreads();

        // ---- grid barrier ----
        if (tid == 0) {
            __threadfence();
            atomicAdd(&g_cnt, 1u);
            unsigned target = (unsigned)(t + 1) * NBLK;
            while (*((volatile unsigned*)&g_cnt) < target) { }
            __threadfence();
        }
        __syncthreads();

        // ---- reload full h(t) into smem ----
        {
            const float4* src = (const float4*)g_hbuf[t & 1];
            float4* dst = (float4*)h_s;
            for (int i = tid; i < HID / 4; i += 256) dst[i] = __ldcg(&src[i]);
        }
        __syncthreads();
    }
}

// ------------------------------------------------------------------
// Y[t][n] = b_y[n] + sum_k H[t][k] * W_y[n][k]
// ------------------------------------------------------------------
__global__ void y_kernel(const float* __restrict__ Wy, const float* __restrict__ by,
                         float* __restrict__ out)
{
    __shared__ float as[64][33];
    __shared__ float ws[64][33];
    __shared__ float bias_s[64];

    const int tid = threadIdx.x;
    const int t0 = blockIdx.x * 64;
    const int n0 = blockIdx.y * 64;
    if (tid < 64) bias_s[tid] = by[n0 + tid];

    const int tx = tid & 15, ty = tid >> 4;
    float acc[4][4];
    #pragma unroll
    for (int e = 0; e < 4; ++e)
        #pragma unroll
        for (int f = 0; f < 4; ++f) acc[e][f] = 0.f;

    for (int kc = 0; kc < HID; kc += 32) {
        __syncthreads();
        #pragma unroll
        for (int i = 0; i < 8; ++i) {
            int l = tid + 256 * i;
            int row = l >> 5, col = l & 31;
            as[row][col] = g_H[(size_t)(t0 + row) * HID + kc + col];
            ws[row][col] = Wy[(size_t)(n0 + row) * HID + kc + col];
        }
        __syncthreads();
        #pragma unroll
        for (int k = 0; k < 32; ++k) {
            float a[4], b[4];
            #pragma unroll
            for (int e = 0; e < 4; ++e) a[e] = as[ty * 4 + e][k];
            #pragma unroll
            for (int f = 0; f < 4; ++f) b[f] = ws[tx * 4 + f][k];
            #pragma unroll
            for (int e = 0; e < 4; ++e)
                #pragma unroll
                for (int f = 0; f < 4; ++f) acc[e][f] = fmaf(a[e], b[f], acc[e][f]);
        }
    }
    __syncthreads();
    #pragma unroll
    for (int e = 0; e < 4; ++e)
        #pragma unroll
        for (int f = 0; f < 4; ++f)
            out[(size_t)(t0 + ty * 4 + e) * NCH + n0 + tx * 4 + f]
                = acc[e][f] + bias_s[tx * 4 + f];
}

// ------------------------------------------------------------------
extern "C" void kernel_launch(void* const* d_in, const int* in_sizes, int n_in,
                              void* d_out, int out_size)
{
    const int*   seq = (const int*)  d_in[0];
    const float* emb = (const float*)d_in[1];
    const float* Wf  = (const float*)d_in[2];
    const float* bf  = (const float*)d_in[3];
    const float* Wi  = (const float*)d_in[4];
    const float* bi  = (const float*)d_in[5];
    const float* Wo  = (const float*)d_in[6];
    const float* bo  = (const float*)d_in[7];
    const float* Wc  = (const float*)d_in[8];
    const float* bc  = (const float*)d_in[9];
    const float* Wy  = (const float*)d_in[10];
    const float* by  = (const float*)d_in[11];
    float* out = (float*)d_out;

    const int dyn_smem = SROWS * HID * 2 + HID * 4;   // 196608 + 8192 = 204800 B
    cudaFuncSetAttribute(lstm_loop, cudaFuncAttributeMaxDynamicSharedMemorySize, dyn_smem);

    init_kernel<<<1, 256>>>();

    prep_kernel<<<4 * HID, 256>>>(Wf, Wi, Wc, Wo);

    dim3 ggx(T_LEN / 64, (4 * HID) / 64);          // 128 x 128
    gx_kernel<<<ggx, 256>>>(seq, emb, Wf, Wi, Wc, Wo, bf, bi, bc, bo);

    lstm_loop<<<NBLK, 256, dyn_smem>>>(out);

    dim3 gy(T_LEN / 64, NCH / 64);                 // 128 x 4
    y_kernel<<<gy, 256>>>(Wy, by, out);
}